// round 4
// baseline (speedup 1.0000x reference)
#include <cuda_runtime.h>

#define BB 2
#define NV 12000
#define NP 32
#define CIN 5
#define CV1 64
#define CV2 128
#define GD 20
#define GC 8000
#define OC1 128
#define R1C 1210      // (10,11,11)
#define OC2 256
#define R2C 180       // (5,6,6)
#define OC3 256
#define R3C 48        // (3,4,4)

__device__ double dS1[CIN], dM1[15];
__device__ double dS2[CV2], dQ2[CV2];
__device__ float  gSc1[CV1], gSh1[CV1];
__device__ float  gF1[BB*NV*CV1];
__device__ float  gY2[BB*NV*CV2];
__device__ float  gSc2[CV2], gSh2[CV2];
__device__ int    gWin[BB*GC];
__device__ float  gSub[BB*CV2*GC];
__device__ float  gRaw1[BB*OC1*R1C];
__device__ float  gSc1c[OC1], gSh1c[OC1], gC1[OC1];
__device__ float  gDelta1[BB*OC1*R1C];
__device__ float  gBg2[8*OC2];
__device__ float  gRaw2[BB*OC2*R2C];
__device__ float  gSc2c[OC2], gSh2c[OC2];
__device__ float  gX2bg[8*OC2];
__device__ float  gDelta2[BB*OC2*R2C];
__device__ float  gNd3[12*OC3];
__device__ float  gRaw3[BB*OC3*R3C];
__device__ float  gSc3c[OC3], gSh3c[OC3];

__global__ void k_init() {
    int i = blockIdx.x*256 + threadIdx.x;
    if (i < BB*GC) gWin[i] = -1;
    if (i < CIN) dS1[i] = 0.0;
    if (i < 15)  dM1[i] = 0.0;
    if (i < CV2) { dS2[i] = 0.0; dQ2[i] = 0.0; }
}

__global__ void k_moments(const float* __restrict__ vf) {
    const int rows = BB*NV*NP;
    double s[CIN], m[15];
    #pragma unroll
    for (int i = 0; i < CIN; i++) s[i] = 0.0;
    #pragma unroll
    for (int t = 0; t < 15; t++) m[t] = 0.0;
    for (int r = blockIdx.x*blockDim.x + threadIdx.x; r < rows; r += gridDim.x*blockDim.x) {
        float x[CIN];
        #pragma unroll
        for (int c = 0; c < CIN; c++) x[c] = vf[r*CIN + c];
        int t = 0;
        #pragma unroll
        for (int i = 0; i < CIN; i++) {
            s[i] += (double)x[i];
            #pragma unroll
            for (int j = i; j < CIN; j++) m[t++] += (double)x[i]*(double)x[j];
        }
    }
    for (int off = 16; off; off >>= 1) {
        #pragma unroll
        for (int i = 0; i < CIN; i++) s[i] += __shfl_down_sync(0xffffffffu, s[i], off);
        #pragma unroll
        for (int t = 0; t < 15; t++)  m[t] += __shfl_down_sync(0xffffffffu, m[t], off);
    }
    if ((threadIdx.x & 31) == 0) {
        #pragma unroll
        for (int i = 0; i < CIN; i++) atomicAdd(&dS1[i], s[i]);
        #pragma unroll
        for (int t = 0; t < 15; t++)  atomicAdd(&dM1[t], m[t]);
    }
}

__global__ void k_bn1(const float* __restrict__ w1, const float* __restrict__ b1,
                      const float* __restrict__ g1, const float* __restrict__ be1) {
    int oc = threadIdx.x; if (oc >= CV1) return;
    const double N = (double)BB*NV*NP;
    double mx[CIN], w[CIN];
    #pragma unroll
    for (int c = 0; c < CIN; c++) { mx[c] = dS1[c]/N; w[c] = (double)w1[oc*CIN+c]; }
    double bb = (double)b1[oc];
    double mu = bb, ey2 = bb*bb;
    #pragma unroll
    for (int c = 0; c < CIN; c++) { mu += w[c]*mx[c]; ey2 += 2.0*bb*w[c]*mx[c]; }
    int t = 0;
    #pragma unroll
    for (int i = 0; i < CIN; i++)
        #pragma unroll
        for (int j = i; j < CIN; j++) {
            double Exx = dM1[t++]/N;
            ey2 += (i==j ? 1.0 : 2.0)*w[i]*w[j]*Exx;
        }
    double var = ey2 - mu*mu;
    double sc = (double)g1[oc]*rsqrt(var + 1e-5);
    gSc1[oc] = (float)sc;
    gSh1[oc] = (float)((double)be1[oc] - mu*sc);
}

__global__ void k_vfe1(const float* __restrict__ vf, const float* __restrict__ w1,
                       const float* __restrict__ b1) {
    __shared__ float sx[NP*CIN];
    int bv = blockIdx.x;
    for (int i = threadIdx.x; i < NP*CIN; i += 64) sx[i] = vf[bv*NP*CIN + i];
    __syncthreads();
    int oc = threadIdx.x;
    float w[CIN];
    #pragma unroll
    for (int c = 0; c < CIN; c++) w[c] = w1[oc*CIN+c];
    float bb = b1[oc], sc = gSc1[oc], sh = gSh1[oc], m = 0.f;
    #pragma unroll 4
    for (int p = 0; p < NP; p++) {
        float y = bb;
        #pragma unroll
        for (int c = 0; c < CIN; c++) y += w[c]*sx[p*CIN+c];
        m = fmaxf(m, fmaxf(y*sc + sh, 0.f));
    }
    gF1[bv*CV1 + oc] = m;
}

#define V2CH 25
__global__ void k_vfe2(const float* __restrict__ w2, const float* __restrict__ b2) {
    __shared__ float sf[CV1];
    int oc = threadIdx.x;
    float w[CV1];
    #pragma unroll
    for (int c = 0; c < CV1; c++) w[c] = w2[oc*CV1+c];
    float bb = b2[oc];
    double s = 0.0, q = 0.0;
    int base = blockIdx.x*V2CH;
    for (int t = 0; t < V2CH; t++) {
        int samp = base + t;
        __syncthreads();
        if (threadIdx.x < CV1) sf[threadIdx.x] = gF1[samp*CV1 + threadIdx.x];
        __syncthreads();
        float y = bb;
        #pragma unroll
        for (int c = 0; c < CV1; c++) y += w[c]*sf[c];
        gY2[samp*CV2 + oc] = y;
        s += (double)y; q += (double)y*(double)y;
    }
    atomicAdd(&dS2[oc], s); atomicAdd(&dQ2[oc], q);
}

__global__ void k_bn2(const float* __restrict__ g2, const float* __restrict__ be2) {
    int oc = threadIdx.x;
    double N = (double)BB*NV;
    double mu = dS2[oc]/N, var = dQ2[oc]/N - mu*mu;
    double sc = (double)g2[oc]*rsqrt(var + 1e-5);
    gSc2[oc] = (float)sc;
    gSh2[oc] = (float)((double)be2[oc] - mu*sc);
}

__global__ void k_win(const int* __restrict__ coords) {
    int i = blockIdx.x*256 + threadIdx.x; if (i >= BB*NV) return;
    int b = i/NV;
    int d = coords[i*3], h = coords[i*3+1], w = coords[i*3+2];
    if ((unsigned)d < GD && (unsigned)h < GD && (unsigned)w < GD)
        atomicMax(&gWin[b*GC + (d*GD + h)*GD + w], i % NV);
}

__global__ void k_scatter() {
    int ch = blockIdx.x, b = blockIdx.y;
    float sc = gSc2[ch], sh = gSh2[ch];
    for (int cell = threadIdx.x; cell < GC; cell += 256) {
        int win = gWin[b*GC + cell];
        float v = 0.f;
        if (win >= 0) v = fmaxf(gY2[(b*NV + win)*CV2 + ch]*sc + sh, 0.f);
        gSub[(b*CV2 + ch)*GC + cell] = v;
    }
}

__global__ void k_conv1(const float* __restrict__ cw1, const float* __restrict__ cb1) {
    __shared__ float sIn[3*23*23];
    __shared__ __align__(16) float sW[27][8];
    int ocg = blockIdx.x, od = blockIdx.y, b = blockIdx.z;
    int tid = threadIdx.x;
    int oh = tid/11, ow = tid%11;
    bool act = tid < 121;
    float acc[8];
    #pragma unroll
    for (int j = 0; j < 8; j++) acc[j] = 0.f;
    for (int ci = 0; ci < CV2; ci++) {
        for (int i = tid; i < 3*529; i += 128) {
            int kd = i/529, r = i%529, yy = r/23 - 1, xx = r%23 - 1;
            int z = 2*od - 1 + kd;
            float v = 0.f;
            if ((unsigned)z < GD && (unsigned)yy < GD && (unsigned)xx < GD)
                v = gSub[(b*CV2 + ci)*GC + (z*GD + yy)*GD + xx];
            sIn[i] = v;
        }
        for (int i = tid; i < 216; i += 128)
            sW[i/8][i%8] = cw1[((ocg*8 + i%8)*CV2 + ci)*27 + i/8];
        __syncthreads();
        if (act) {
            #pragma unroll
            for (int kd = 0; kd < 3; kd++)
            #pragma unroll
            for (int kh = 0; kh < 3; kh++)
            #pragma unroll
            for (int kw = 0; kw < 3; kw++) {
                float iv = sIn[kd*529 + (2*oh + kh)*23 + 2*ow + kw];
                const float4* wp = (const float4*)sW[kd*9 + kh*3 + kw];
                float4 a = wp[0], c = wp[1];
                acc[0] += iv*a.x; acc[1] += iv*a.y; acc[2] += iv*a.z; acc[3] += iv*a.w;
                acc[4] += iv*c.x; acc[5] += iv*c.y; acc[6] += iv*c.z; acc[7] += iv*c.w;
            }
        }
        __syncthreads();
    }
    if (act)
        #pragma unroll
        for (int j = 0; j < 8; j++) {
            int oc = ocg*8 + j;
            gRaw1[(b*OC1 + oc)*R1C + od*121 + tid] = acc[j] + cb1[oc];
        }
}

__global__ void k_bnc1(const float* __restrict__ cb1, const float* __restrict__ cg1,
                       const float* __restrict__ cbe1) {
    int oc = blockIdx.x, tid = threadIdx.x;
    double s = 0.0, q = 0.0;
    for (int i = tid; i < BB*R1C; i += 256) {
        float v = gRaw1[(i/R1C*OC1 + oc)*R1C + i%R1C];
        s += (double)v; q += (double)v*(double)v;
    }
    __shared__ double ss[256], sq[256];
    ss[tid] = s; sq[tid] = q; __syncthreads();
    for (int st = 128; st; st >>= 1) {
        if (tid < st) { ss[tid] += ss[tid+st]; sq[tid] += sq[tid+st]; }
        __syncthreads();
    }
    if (tid == 0) {
        double N = 81920.0, bgn = N - BB*R1C;
        double bg = (double)cb1[oc];
        double mu = (ss[0] + bg*bgn)/N;
        double var = (sq[0] + bg*bg*bgn)/N - mu*mu;
        double sc = (double)cg1[oc]*rsqrt(var + 1e-5);
        double sh = (double)cbe1[oc] - mu*sc;
        gSc1c[oc] = (float)sc; gSh1c[oc] = (float)sh;
        double c1 = bg*sc + sh;
        gC1[oc] = (float)(c1 > 0.0 ? c1 : 0.0);
    }
}

__global__ void k_delta1() {
    int i = blockIdx.x*256 + threadIdx.x;
    if (i >= BB*OC1*R1C) return;
    int oc = (i/R1C) % OC1;
    gDelta1[i] = fmaxf(gRaw1[i]*gSc1c[oc] + gSh1c[oc], 0.f) - gC1[oc];
}

__global__ void k_bg2(const float* __restrict__ cw2, const float* __restrict__ cb2) {
    __shared__ float sc1[OC1];
    int pat = blockIdx.x, oc = threadIdx.x;
    for (int i = oc; i < OC1; i += 256) sc1[i] = gC1[i];
    __syncthreads();
    int fd = (pat>>2)&1, fh = (pat>>1)&1, fw = pat&1;
    float acc = 0.f;
    for (int ci = 0; ci < OC1; ci++) {
        float cv = sc1[ci];
        const float* wp = &cw2[(oc*OC1 + ci)*27];
        #pragma unroll
        for (int kd = 0; kd < 3; kd++)
        #pragma unroll
        for (int kh = 0; kh < 3; kh++)
        #pragma unroll
        for (int kw = 0; kw < 3; kw++) {
            if ((fd && kd==0) || (fh && kh==0) || (fw && kw==0)) continue;
            acc += wp[kd*9 + kh*3 + kw]*cv;
        }
    }
    gBg2[pat*OC2 + oc] = cb2[oc] + acc;
}

__global__ void k_conv2(const float* __restrict__ cw2) {
    __shared__ float sIn[3*169];
    __shared__ __align__(16) float sW[27][8];
    int ocg = blockIdx.x, od = blockIdx.y, b = blockIdx.z;
    int tid = threadIdx.x;
    int oh = tid/6, ow = tid%6;
    bool act = tid < 36;
    float acc[8];
    #pragma unroll
    for (int j = 0; j < 8; j++) acc[j] = 0.f;
    for (int ci = 0; ci < OC1; ci++) {
        for (int i = tid; i < 3*169; i += 64) {
            int kd = i/169, r = i%169, yy = r/13 - 1, xx = r%13 - 1;
            int z = 2*od - 1 + kd;
            float v = 0.f;
            if ((unsigned)z < 10u && (unsigned)yy < 11u && (unsigned)xx < 11u)
                v = gDelta1[(b*OC1 + ci)*R1C + z*121 + yy*11 + xx];
            sIn[i] = v;
        }
        for (int i = tid; i < 216; i += 64)
            sW[i/8][i%8] = cw2[((ocg*8 + i%8)*OC1 + ci)*27 + i/8];
        __syncthreads();
        if (act) {
            #pragma unroll
            for (int kd = 0; kd < 3; kd++)
            #pragma unroll
            for (int kh = 0; kh < 3; kh++)
            #pragma unroll
            for (int kw = 0; kw < 3; kw++) {
                float iv = sIn[kd*169 + (2*oh + kh)*13 + 2*ow + kw];
                const float4* wp = (const float4*)sW[kd*9 + kh*3 + kw];
                float4 a = wp[0], c = wp[1];
                acc[0] += iv*a.x; acc[1] += iv*a.y; acc[2] += iv*a.z; acc[3] += iv*a.w;
                acc[4] += iv*c.x; acc[5] += iv*c.y; acc[6] += iv*c.z; acc[7] += iv*c.w;
            }
        }
        __syncthreads();
    }
    if (act) {
        int pat = ((od==0)<<2) | ((oh==0)<<1) | (ow==0);
        #pragma unroll
        for (int j = 0; j < 8; j++) {
            int oc = ocg*8 + j;
            gRaw2[(b*OC2 + oc)*R2C + od*36 + tid] = acc[j] + gBg2[pat*OC2 + oc];
        }
    }
}

__global__ void k_bnc2(const float* __restrict__ cg2, const float* __restrict__ cbe2) {
    int oc = blockIdx.x, tid = threadIdx.x;
    double s = 0.0, q = 0.0;
    for (int i = tid; i < BB*R2C; i += 128) {
        float v = gRaw2[(i/R2C*OC2 + oc)*R2C + i%R2C];
        s += (double)v; q += (double)v*(double)v;
    }
    __shared__ double ss[128], sq[128];
    ss[tid] = s; sq[tid] = q; __syncthreads();
    for (int st = 64; st; st >>= 1) {
        if (tid < st) { ss[tid] += ss[tid+st]; sq[tid] += sq[tid+st]; }
        __syncthreads();
    }
    if (tid == 0) {
        double S = ss[0], Q = sq[0];
        for (int pat = 0; pat < 8; pat++) {
            int fd = (pat>>2)&1, fh = (pat>>1)&1, fw = pat&1;
            int cd = fd?1:4, ch = fh?1:31, cw = fw?1:31;
            int dh = fh?1:5, dw = fw?1:5;
            double cnt = 2.0*cd*(ch*cw - dh*dw);
            double bg = (double)gBg2[pat*OC2 + oc];
            S += bg*cnt; Q += bg*bg*cnt;
        }
        double N = 10240.0;
        double mu = S/N, var = Q/N - mu*mu;
        double sc = (double)cg2[oc]*rsqrt(var + 1e-5);
        double sh = (double)cbe2[oc] - mu*sc;
        gSc2c[oc] = (float)sc; gSh2c[oc] = (float)sh;
        for (int pat = 0; pat < 8; pat++) {
            double v = (double)gBg2[pat*OC2 + oc]*sc + sh;
            gX2bg[pat*OC2 + oc] = (float)(v > 0.0 ? v : 0.0);
        }
    }
}

__global__ void k_delta2() {
    int i = blockIdx.x*256 + threadIdx.x;
    if (i >= BB*OC2*R2C) return;
    int r = i % R2C, oc = (i/R2C) % OC2;
    int od = r/36, oh = (r%36)/6, ow = r%6;
    int pat = ((od==0)<<2) | ((oh==0)<<1) | (ow==0);
    gDelta2[i] = fmaxf(gRaw2[i]*gSc2c[oc] + gSh2c[oc], 0.f) - gX2bg[pat*OC2 + oc];
}

__global__ void k_nd3(const float* __restrict__ cw3, const float* __restrict__ cb3) {
    __shared__ float sbg[8*OC2];
    int cs = blockIdx.x, oc = threadIdx.x;
    for (int i = oc; i < 8*OC2; i += 256) sbg[i] = gX2bg[i];
    __syncthreads();
    int dc = cs>>2, hc = (cs>>1)&1, wc = cs&1;
    float acc = 0.f;
    for (int ci = 0; ci < OC2; ci++) {
        const float* wp = &cw3[(oc*OC2 + ci)*27];
        #pragma unroll
        for (int kd = 0; kd < 3; kd++) {
            int zpad = (dc==1 && kd==0) || (dc==2 && kd==2);
            int zb = (dc==1 && kd==1);
            #pragma unroll
            for (int kh = 0; kh < 3; kh++) {
                int ypad = hc && kh==0, yb = hc && kh==1;
                #pragma unroll
                for (int kw = 0; kw < 3; kw++) {
                    int xpad = wc && kw==0, xb = wc && kw==1;
                    if (zpad || ypad || xpad) continue;
                    acc += wp[kd*9 + kh*3 + kw]*sbg[((zb<<2)|(yb<<1)|xb)*OC2 + ci];
                }
            }
        }
    }
    gNd3[cs*OC3 + oc] = cb3[oc] + acc;
}

__global__ void k_conv3(const float* __restrict__ cw3) {
    __shared__ float sIn[3*81];
    __shared__ __align__(16) float sW[27][8];
    int ocg = blockIdx.x, od = blockIdx.y, b = blockIdx.z;
    int tid = threadIdx.x;
    int oh = tid/4, ow = tid%4;
    bool act = tid < 16;
    float acc[8];
    #pragma unroll
    for (int j = 0; j < 8; j++) acc[j] = 0.f;
    for (int ci = 0; ci < OC2; ci++) {
        for (int i = tid; i < 3*81; i += 64) {
            int kd = i/81, r = i%81, yy = r/9 - 1, xx = r%9 - 1;
            int z = 2*od - 1 + kd;
            float v = 0.f;
            if ((unsigned)z < 5u && (unsigned)yy < 6u && (unsigned)xx < 6u)
                v = gDelta2[(b*OC2 + ci)*R2C + z*36 + yy*6 + xx];
            sIn[i] = v;
        }
        for (int i = tid; i < 216; i += 64)
            sW[i/8][i%8] = cw3[((ocg*8 + i%8)*OC2 + ci)*27 + i/8];
        __syncthreads();
        if (act) {
            #pragma unroll
            for (int kd = 0; kd < 3; kd++)
            #pragma unroll
            for (int kh = 0; kh < 3; kh++)
            #pragma unroll
            for (int kw = 0; kw < 3; kw++) {
                float iv = sIn[kd*81 + (2*oh + kh)*9 + 2*ow + kw];
                const float4* wp = (const float4*)sW[kd*9 + kh*3 + kw];
                float4 a = wp[0], c = wp[1];
                acc[0] += iv*a.x; acc[1] += iv*a.y; acc[2] += iv*a.z; acc[3] += iv*a.w;
                acc[4] += iv*c.x; acc[5] += iv*c.y; acc[6] += iv*c.z; acc[7] += iv*c.w;
            }
        }
        __syncthreads();
    }
    if (act) {
        int dc = (od==0) ? 1 : ((od==2) ? 2 : 0);
        int cs = dc*4 + ((oh==0)<<1) + (ow==0);
        #pragma unroll
        for (int j = 0; j < 8; j++) {
            int oc = ocg*8 + j;
            gRaw3[(b*OC3 + oc)*R3C + od*16 + tid] = acc[j] + gNd3[cs*OC3 + oc];
        }
    }
}

__global__ void k_bnc3(const float* __restrict__ cg3, const float* __restrict__ cbe3) {
    int oc = blockIdx.x, tid = threadIdx.x;
    double s = 0.0, q = 0.0;
    for (int i = tid; i < BB*R3C; i += 128) {
        float v = gRaw3[(i/R3C*OC3 + oc)*R3C + i%R3C];
        s += (double)v; q += (double)v*(double)v;
    }
    __shared__ double ss[128], sq[128];
    ss[tid] = s; sq[tid] = q; __syncthreads();
    for (int st = 64; st; st >>= 1) {
        if (tid < st) { ss[tid] += ss[tid+st]; sq[tid] += sq[tid+st]; }
        __syncthreads();
    }
    if (tid == 0) {
        double S = ss[0], Q = sq[0];
        for (int cs = 0; cs < 12; cs++) {
            int hc = (cs>>1)&1, wc = cs&1;
            int ch = hc?1:15, cw = wc?1:15, dh = hc?1:3, dw = wc?1:3;
            double cnt = 2.0*(ch*cw - dh*dw);
            double bg = (double)gNd3[cs*OC3 + oc];
            S += bg*cnt; Q += bg*bg*cnt;
        }
        double N = 1536.0;
        double mu = S/N, var = Q/N - mu*mu;
        double sc = (double)cg3[oc]*rsqrt(var + 1e-5);
        gSc3c[oc] = (float)sc;
        gSh3c[oc] = (float)((double)cbe3[oc] - mu*sc);
    }
}

__global__ void k_out(float* __restrict__ out) {
    int i = blockIdx.x*256 + threadIdx.x;
    if (i >= BB*OC3*3*256) return;
    int hw = i % 256, od = (i/256) % 3, oc = (i/768) % OC3, b = i/(768*OC3);
    int oh = hw/16, ow = hw%16;
    float sc = gSc3c[oc], sh = gSh3c[oc], raw;
    if (oh < 4 && ow < 4)
        raw = gRaw3[(b*OC3 + oc)*R3C + od*16 + oh*4 + ow];
    else {
        int dc = (od==0) ? 1 : ((od==2) ? 2 : 0);
        raw = gNd3[(dc*4 + ((oh==0)<<1) + (ow==0))*OC3 + oc];
    }
    out[i] = fmaxf(raw*sc + sh, 0.f);
}

extern "C" void kernel_launch(void* const* d_in, const int* in_sizes, int n_in,
                              void* d_out, int out_size) {
    // metadata order: vf, coords, [D,H,W scalars], w1,b1,g1,be1, w2,b2,g2,be2,
    // cw1,cb1,cg1,cbe1, cw2,cb2,cg2,cbe2, cw3,cb3,cg3,cbe3
    int base = (n_in >= 25) ? 5 : 2;   // skip D,H,W scalars if present
    const float* vf   = (const float*)d_in[0];
    const int*  coords= (const int*)d_in[1];
    const float* w1 = (const float*)d_in[base+0];
    const float* b1 = (const float*)d_in[base+1];
    const float* g1 = (const float*)d_in[base+2];
    const float* be1= (const float*)d_in[base+3];
    const float* w2 = (const float*)d_in[base+4];
    const float* b2 = (const float*)d_in[base+5];
    const float* g2 = (const float*)d_in[base+6];
    const float* be2= (const float*)d_in[base+7];
    const float* cw1= (const float*)d_in[base+8];
    const float* cb1= (const float*)d_in[base+9];
    const float* cg1= (const float*)d_in[base+10];
    const float* cbe1=(const float*)d_in[base+11];
    const float* cw2= (const float*)d_in[base+12];
    const float* cb2= (const float*)d_in[base+13];
    const float* cg2= (const float*)d_in[base+14];
    const float* cbe2=(const float*)d_in[base+15];
    const float* cw3= (const float*)d_in[base+16];
    const float* cb3= (const float*)d_in[base+17];
    const float* cg3= (const float*)d_in[base+18];
    const float* cbe3=(const float*)d_in[base+19];
    float* out = (float*)d_out;

    k_init<<<64, 256>>>();
    k_moments<<<256, 256>>>(vf);
    k_bn1<<<1, 64>>>(w1, b1, g1, be1);
    k_vfe1<<<BB*NV, 64>>>(vf, w1, b1);
    k_vfe2<<<BB*NV/V2CH, 128>>>(w2, b2);
    k_bn2<<<1, 128>>>(g2, be2);
    k_win<<<(BB*NV + 255)/256, 256>>>(coords);
    k_scatter<<<dim3(CV2, BB), 256>>>();
    k_conv1<<<dim3(16, 10, BB), 128>>>(cw1, cb1);
    k_bnc1<<<OC1, 256>>>(cb1, cg1, cbe1);
    k_delta1<<<(BB*OC1*R1C + 255)/256, 256>>>();
    k_bg2<<<8, 256>>>(cw2, cb2);
    k_conv2<<<dim3(32, 5, BB), 64>>>(cw2);
    k_bnc2<<<OC2, 128>>>(cg2, cbe2);
    k_delta2<<<(BB*OC2*R2C + 255)/256, 256>>>();
    k_nd3<<<12, 256>>>(cw3, cb3);
    k_conv3<<<dim3(32, 3, BB), 64>>>(cw3);
    k_bnc3<<<OC3, 128>>>(cg3, cbe3);
    k_out<<<(BB*OC3*3*256 + 255)/256, 256>>>(out);
}

// round 6
// speedup vs baseline: 1.0532x; 1.0532x over previous
#include <cuda_runtime.h>

#define BB 2
#define NV 12000
#define NP 32
#define CIN 5
#define CV1 64
#define CV2 128
#define GD 20
#define GC 8000
#define OC1 128
#define R1C 1210      // (10,11,11)
#define OC2 256
#define R2C 180       // (5,6,6)
#define OC3 256
#define R3C 48        // (3,4,4)

__device__ double dS1[CIN], dM1[15];
__device__ double dS2[CV2], dQ2[CV2];
__device__ float  gSc1[CV1], gSh1[CV1];
__device__ float  gY2[BB*NV*CV2];
__device__ float  gSc2[CV2], gSh2[CV2];
__device__ int    gWin[BB*GC];
__device__ float  gSub[BB*CV2*GC];
__device__ float  gRaw1[BB*OC1*R1C];
__device__ float  gSc1c[OC1], gSh1c[OC1], gC1[OC1];
__device__ float  gDelta1[BB*OC1*R1C];
__device__ float  gBg2[8*OC2];
__device__ float  gRaw2[BB*OC2*R2C];
__device__ float  gSc2c[OC2], gSh2c[OC2];
__device__ float  gX2bg[8*OC2];
__device__ float  gDelta2[BB*OC2*R2C];
__device__ float  gNd3[12*OC3];
__device__ float  gP3a[BB*OC3*R3C];
__device__ float  gP3b[BB*OC3*R3C];
__device__ float  gSc3c[OC3], gSh3c[OC3];
__device__ float  cwT1[CV2*27*OC1];
__device__ float  cwT2[OC1*27*OC2];
__device__ float  cwT3[OC2*27*OC3];

// ---- packed f32x2 helpers ----
__device__ __forceinline__ unsigned long long pack2(float v) {
    unsigned long long p;
    asm("mov.b64 %0, {%1, %1};" : "=l"(p) : "r"(__float_as_uint(v)));
    return p;
}
__device__ __forceinline__ unsigned long long ffma2(unsigned long long a,
                                                    unsigned long long b,
                                                    unsigned long long c) {
    unsigned long long d;
    asm("fma.rn.f32x2 %0, %1, %2, %3;" : "=l"(d) : "l"(a), "l"(b), "l"(c));
    return d;
}
__device__ __forceinline__ float2 unpack2(unsigned long long p) {
    unsigned lo, hi;
    asm("mov.b64 {%0, %1}, %2;" : "=r"(lo), "=r"(hi) : "l"(p));
    float2 r; r.x = __uint_as_float(lo); r.y = __uint_as_float(hi);
    return r;
}

__global__ void k_init() {
    int i = blockIdx.x*256 + threadIdx.x;
    if (i < BB*GC) gWin[i] = -1;
    if (i < CIN) dS1[i] = 0.0;
    if (i < 15)  dM1[i] = 0.0;
    if (i < CV2) { dS2[i] = 0.0; dQ2[i] = 0.0; }
}

// transpose weights: dst[(ci*27+k)*OC + oc] = src[(oc*IC+ci)*27 + k]
__global__ void k_wT(const float* __restrict__ src, float* __restrict__ dst,
                     int OC, int IC) {
    int i = blockIdx.x*256 + threadIdx.x;
    if (i >= OC*IC*27) return;
    int oc = i % OC, k = (i/OC) % 27, ci = i/(OC*27);
    dst[i] = src[(oc*IC + ci)*27 + k];
}

__global__ void k_moments(const float* __restrict__ vf) {
    const int rows = BB*NV*NP;
    double s[CIN], m[15];
    #pragma unroll
    for (int i = 0; i < CIN; i++) s[i] = 0.0;
    #pragma unroll
    for (int t = 0; t < 15; t++) m[t] = 0.0;
    for (int r = blockIdx.x*blockDim.x + threadIdx.x; r < rows; r += gridDim.x*blockDim.x) {
        float x[CIN];
        #pragma unroll
        for (int c = 0; c < CIN; c++) x[c] = vf[r*CIN + c];
        int t = 0;
        #pragma unroll
        for (int i = 0; i < CIN; i++) {
            s[i] += (double)x[i];
            #pragma unroll
            for (int j = i; j < CIN; j++) m[t++] += (double)x[i]*(double)x[j];
        }
    }
    for (int off = 16; off; off >>= 1) {
        #pragma unroll
        for (int i = 0; i < CIN; i++) s[i] += __shfl_down_sync(0xffffffffu, s[i], off);
        #pragma unroll
        for (int t = 0; t < 15; t++)  m[t] += __shfl_down_sync(0xffffffffu, m[t], off);
    }
    __shared__ double red[8][20];
    int w = threadIdx.x >> 5, l = threadIdx.x & 31;
    if (l == 0) {
        #pragma unroll
        for (int i = 0; i < CIN; i++) red[w][i] = s[i];
        #pragma unroll
        for (int t = 0; t < 15; t++)  red[w][5+t] = m[t];
    }
    __syncthreads();
    if (threadIdx.x < 20) {
        double a = 0.0;
        #pragma unroll
        for (int ww = 0; ww < 8; ww++) a += red[ww][threadIdx.x];
        if (threadIdx.x < 5) atomicAdd(&dS1[threadIdx.x], a);
        else                 atomicAdd(&dM1[threadIdx.x-5], a);
    }
}

__global__ void k_bn1(const float* __restrict__ w1, const float* __restrict__ b1,
                      const float* __restrict__ g1, const float* __restrict__ be1) {
    int oc = threadIdx.x; if (oc >= CV1) return;
    const double N = (double)BB*NV*NP;
    double mx[CIN], w[CIN];
    #pragma unroll
    for (int c = 0; c < CIN; c++) { mx[c] = dS1[c]/N; w[c] = (double)w1[oc*CIN+c]; }
    double bb = (double)b1[oc];
    double mu = bb, ey2 = bb*bb;
    #pragma unroll
    for (int c = 0; c < CIN; c++) { mu += w[c]*mx[c]; ey2 += 2.0*bb*w[c]*mx[c]; }
    int t = 0;
    #pragma unroll
    for (int i = 0; i < CIN; i++)
        #pragma unroll
        for (int j = i; j < CIN; j++) {
            double Exx = dM1[t++]/N;
            ey2 += (i==j ? 1.0 : 2.0)*w[i]*w[j]*Exx;
        }
    double var = ey2 - mu*mu;
    double sc = (double)g1[oc]*rsqrt(var + 1e-5);
    gSc1[oc] = (float)sc;
    gSh1[oc] = (float)((double)be1[oc] - mu*sc);
}

// fused VFE1+VFE2: per-voxel f1[64] in smem, then y2[128]; stats via block-chunked atomics
#define VCH 24
__global__ void k_vfe(const float* __restrict__ vf,
                      const float* __restrict__ w1, const float* __restrict__ b1,
                      const float* __restrict__ w2, const float* __restrict__ b2) {
    __shared__ float sx[NP*CIN];
    __shared__ float sf1[CV1];
    int tid = threadIdx.x;
    float w2r[CV1];
    #pragma unroll
    for (int c = 0; c < CV1; c++) w2r[c] = w2[tid*CV1 + c];
    float bb2 = b2[tid];
    float w1r[CIN]; float bb1 = 0.f, sc1 = 0.f, sh1 = 0.f;
    if (tid < CV1) {
        #pragma unroll
        for (int c = 0; c < CIN; c++) w1r[c] = w1[tid*CIN + c];
        bb1 = b1[tid]; sc1 = gSc1[tid]; sh1 = gSh1[tid];
    }
    double s = 0.0, q = 0.0;
    int base = blockIdx.x*VCH;
    for (int t = 0; t < VCH; t++) {
        int v = base + t;
        __syncthreads();
        for (int i = tid; i < NP*CIN; i += 128) sx[i] = vf[v*NP*CIN + i];
        __syncthreads();
        if (tid < CV1) {
            float m = 0.f;
            #pragma unroll 4
            for (int p = 0; p < NP; p++) {
                float y = bb1;
                #pragma unroll
                for (int c = 0; c < CIN; c++) y += w1r[c]*sx[p*CIN + c];
                m = fmaxf(m, fmaxf(y*sc1 + sh1, 0.f));
            }
            sf1[tid] = m;
        }
        __syncthreads();
        float y = bb2;
        #pragma unroll
        for (int c = 0; c < CV1; c++) y += w2r[c]*sf1[c];
        gY2[v*CV2 + tid] = y;
        s += (double)y; q += (double)y*(double)y;
    }
    atomicAdd(&dS2[tid], s); atomicAdd(&dQ2[tid], q);
}

__global__ void k_bn2(const float* __restrict__ g2, const float* __restrict__ be2) {
    int oc = threadIdx.x;
    double N = (double)BB*NV;
    double mu = dS2[oc]/N, var = dQ2[oc]/N - mu*mu;
    double sc = (double)g2[oc]*rsqrt(var + 1e-5);
    gSc2[oc] = (float)sc;
    gSh2[oc] = (float)((double)be2[oc] - mu*sc);
}

__global__ void k_win(const int* __restrict__ coords) {
    int i = blockIdx.x*256 + threadIdx.x; if (i >= BB*NV) return;
    int b = i/NV;
    int d = coords[i*3], h = coords[i*3+1], w = coords[i*3+2];
    if ((unsigned)d < GD && (unsigned)h < GD && (unsigned)w < GD)
        atomicMax(&gWin[b*GC + (d*GD + h)*GD + w], i % NV);
}

__global__ void k_scatter() {
    int ch = blockIdx.x, b = blockIdx.y;
    float sc = gSc2[ch], sh = gSh2[ch];
    for (int cell = threadIdx.x; cell < GC; cell += 256) {
        int win = gWin[b*GC + cell];
        float v = 0.f;
        if (win >= 0) v = fmaxf(gY2[(b*NV + win)*CV2 + ch]*sc + sh, 0.f);
        gSub[(b*CV2 + ch)*GC + cell] = v;
    }
}

// conv1: grid (16 ocg, 10 od, 2 b), 128 thr; CIB=4; f32x2 inner loop
__global__ void k_conv1(const float* __restrict__ cb1) {
    __shared__ float sIn[4*1587];
    __shared__ __align__(16) float sW[4*27*8];
    int ocg = blockIdx.x, od = blockIdx.y, b = blockIdx.z;
    int tid = threadIdx.x;
    int oh = tid/11, ow = tid%11;
    bool act = tid < 121;
    unsigned long long acc[4] = {0ull, 0ull, 0ull, 0ull};
    for (int c0 = 0; c0 < CV2; c0 += 4) {
        __syncthreads();
        for (int i = tid; i < 4*1587; i += 128) {
            int cib = i/1587, r = i%1587;
            int kd = r/529, rr = r%529, yy = rr/23 - 1, xx = rr%23 - 1;
            int z = 2*od - 1 + kd;
            float v = 0.f;
            if ((unsigned)z < GD && (unsigned)yy < GD && (unsigned)xx < GD)
                v = gSub[(b*CV2 + c0 + cib)*GC + (z*GD + yy)*GD + xx];
            sIn[i] = v;
        }
        for (int i = tid; i < 4*216; i += 128) {
            int cib = i/216, r = i%216, k = r/8, j = r%8;
            sW[(cib*27 + k)*8 + j] = cwT1[((c0 + cib)*27 + k)*OC1 + ocg*8 + j];
        }
        __syncthreads();
        if (act) {
            #pragma unroll
            for (int cib = 0; cib < 4; cib++) {
                const float* bp = sIn + cib*1587;
                #pragma unroll
                for (int kd = 0; kd < 3; kd++)
                #pragma unroll
                for (int kh = 0; kh < 3; kh++)
                #pragma unroll
                for (int kw = 0; kw < 3; kw++) {
                    float iv = bp[kd*529 + (2*oh + kh)*23 + 2*ow + kw];
                    unsigned long long pv = pack2(iv);
                    const ulonglong2* wp =
                        (const ulonglong2*)&sW[(cib*27 + kd*9 + kh*3 + kw)*8];
                    ulonglong2 wa = wp[0], wb = wp[1];
                    acc[0] = ffma2(pv, wa.x, acc[0]);
                    acc[1] = ffma2(pv, wa.y, acc[1]);
                    acc[2] = ffma2(pv, wb.x, acc[2]);
                    acc[3] = ffma2(pv, wb.y, acc[3]);
                }
            }
        }
    }
    if (act) {
        float2 u0 = unpack2(acc[0]), u1 = unpack2(acc[1]);
        float2 u2 = unpack2(acc[2]), u3 = unpack2(acc[3]);
        float vals[8] = {u0.x,u0.y,u1.x,u1.y,u2.x,u2.y,u3.x,u3.y};
        #pragma unroll
        for (int j = 0; j < 8; j++) {
            int oc = ocg*8 + j;
            gRaw1[(b*OC1 + oc)*R1C + od*121 + tid] = vals[j] + cb1[oc];
        }
    }
}

__global__ void k_bnc1(const float* __restrict__ cb1, const float* __restrict__ cg1,
                       const float* __restrict__ cbe1) {
    int oc = blockIdx.x, tid = threadIdx.x;
    double s = 0.0, q = 0.0;
    for (int i = tid; i < BB*R1C; i += 256) {
        float v = gRaw1[(i/R1C*OC1 + oc)*R1C + i%R1C];
        s += (double)v; q += (double)v*(double)v;
    }
    __shared__ double ss[256], sq[256];
    ss[tid] = s; sq[tid] = q; __syncthreads();
    for (int st = 128; st; st >>= 1) {
        if (tid < st) { ss[tid] += ss[tid+st]; sq[tid] += sq[tid+st]; }
        __syncthreads();
    }
    if (tid == 0) {
        double N = 81920.0, bgn = N - BB*R1C;
        double bg = (double)cb1[oc];
        double mu = (ss[0] + bg*bgn)/N;
        double var = (sq[0] + bg*bg*bgn)/N - mu*mu;
        double sc = (double)cg1[oc]*rsqrt(var + 1e-5);
        double sh = (double)cbe1[oc] - mu*sc;
        gSc1c[oc] = (float)sc; gSh1c[oc] = (float)sh;
        double c1 = bg*sc + sh;
        gC1[oc] = (float)(c1 > 0.0 ? c1 : 0.0);
    }
}

__global__ void k_delta1() {
    int i = blockIdx.x*256 + threadIdx.x;
    if (i >= BB*OC1*R1C) return;
    int oc = (i/R1C) % OC1;
    gDelta1[i] = fmaxf(gRaw1[i]*gSc1c[oc] + gSh1c[oc], 0.f) - gC1[oc];
}

__global__ void k_bg2(const float* __restrict__ cw2, const float* __restrict__ cb2) {
    __shared__ float sc1[OC1];
    int pat = blockIdx.x, oc = threadIdx.x;
    for (int i = oc; i < OC1; i += 256) sc1[i] = gC1[i];
    __syncthreads();
    int fd = (pat>>2)&1, fh = (pat>>1)&1, fw = pat&1;
    float acc = 0.f;
    for (int ci = 0; ci < OC1; ci++) {
        float cv = sc1[ci];
        const float* wp = &cw2[(oc*OC1 + ci)*27];
        #pragma unroll
        for (int kd = 0; kd < 3; kd++)
        #pragma unroll
        for (int kh = 0; kh < 3; kh++)
        #pragma unroll
        for (int kw = 0; kw < 3; kw++) {
            if ((fd && kd==0) || (fh && kh==0) || (fw && kw==0)) continue;
            acc += wp[kd*9 + kh*3 + kw]*cv;
        }
    }
    gBg2[pat*OC2 + oc] = cb2[oc] + acc;
}

// conv2: grid (64 ocq(4oc), 2 b), 192 thr; CIB=4; padded smem halo; f32x2
__global__ void k_conv2() {
    __shared__ float sIn[4*1859];               // 11 x 13 x 13 per ci
    __shared__ __align__(16) float sW[4*27*4];
    int ocq = blockIdx.x, b = blockIdx.y;
    int tid = threadIdx.x;
    int pos = tid;
    int od = pos/36, oh = (pos%36)/6, ow = pos%6;
    bool act = tid < R2C;
    unsigned long long a0 = 0ull, a1 = 0ull;
    for (int c0 = 0; c0 < OC1; c0 += 4) {
        __syncthreads();
        for (int i = tid; i < 4*1859; i += 192) {
            int cib = i/1859, r = i%1859;
            int zz = r/169 - 1, rr = r%169, yy = rr/13 - 1, xx = rr%13 - 1;
            float v = 0.f;
            if ((unsigned)zz < 10u && (unsigned)yy < 11u && (unsigned)xx < 11u)
                v = gDelta1[(b*OC1 + c0 + cib)*R1C + zz*121 + yy*11 + xx];
            sIn[i] = v;
        }
        for (int i = tid; i < 4*108; i += 192) {
            int cib = i/108, r = i%108, k = r/4, j = r%4;
            sW[(cib*27 + k)*4 + j] = cwT2[((c0 + cib)*27 + k)*OC2 + ocq*4 + j];
        }
        __syncthreads();
        if (act) {
            #pragma unroll
            for (int cib = 0; cib < 4; cib++) {
                const float* bp = sIn + cib*1859;
                #pragma unroll
                for (int kd = 0; kd < 3; kd++)
                #pragma unroll
                for (int kh = 0; kh < 3; kh++)
                #pragma unroll
                for (int kw = 0; kw < 3; kw++) {
                    float iv = bp[(2*od + kd)*169 + (2*oh + kh)*13 + 2*ow + kw];
                    unsigned long long pv = pack2(iv);
                    const ulonglong2* wp =
                        (const ulonglong2*)&sW[(cib*27 + kd*9 + kh*3 + kw)*4];
                    ulonglong2 w = *wp;
                    a0 = ffma2(pv, w.x, a0);
                    a1 = ffma2(pv, w.y, a1);
                }
            }
        }
    }
    if (act) {
        int pat = ((od==0)<<2) | ((oh==0)<<1) | (ow==0);
        float2 u0 = unpack2(a0), u1 = unpack2(a1);
        float vals[4] = {u0.x, u0.y, u1.x, u1.y};
        #pragma unroll
        for (int j = 0; j < 4; j++) {
            int oc = ocq*4 + j;
            gRaw2[(b*OC2 + oc)*R2C + pos] = vals[j] + gBg2[pat*OC2 + oc];
        }
    }
}

__global__ void k_bnc2(const float* __restrict__ cg2, const float* __restrict__ cbe2) {
    int oc = blockIdx.x, tid = threadIdx.x;
    double s = 0.0, q = 0.0;
    for (int i = tid; i < BB*R2C; i += 128) {
        float v = gRaw2[(i/R2C*OC2 + oc)*R2C + i%R2C];
        s += (double)v; q += (double)v*(double)v;
    }
    __shared__ double ss[128], sq[128];
    ss[tid] = s; sq[tid] = q; __syncthreads();
    for (int st = 64; st; st >>= 1) {
        if (tid < st) { ss[tid] += ss[tid+st]; sq[tid] += sq[tid+st]; }
        __syncthreads();
    }
    if (tid == 0) {
        double S = ss[0], Q = sq[0];
        for (int pat = 0; pat < 8; pat++) {
            int fd = (pat>>2)&1, fh = (pat>>1)&1, fw = pat&1;
            int cd = fd?1:4, ch = fh?1:31, cw = fw?1:31;
            int dh = fh?1:5, dw = fw?1:5;
            double cnt = 2.0*cd*(ch*cw - dh*dw);
            double bg = (double)gBg2[pat*OC2 + oc];
            S += bg*cnt; Q += bg*bg*cnt;
        }
        double N = 10240.0;
        double mu = S/N, var = Q/N - mu*mu;
        double sc = (double)cg2[oc]*rsqrt(var + 1e-5);
        double sh = (double)cbe2[oc] - mu*sc;
        gSc2c[oc] = (float)sc; gSh2c[oc] = (float)sh;
        for (int pat = 0; pat < 8; pat++) {
            double v = (double)gBg2[pat*OC2 + oc]*sc + sh;
            gX2bg[pat*OC2 + oc] = (float)(v > 0.0 ? v : 0.0);
        }
    }
}

__global__ void k_delta2() {
    int i = blockIdx.x*256 + threadIdx.x;
    if (i >= BB*OC2*R2C) return;
    int r = i % R2C, oc = (i/R2C) % OC2;
    int od = r/36, oh = (r%36)/6, ow = r%6;
    int pat = ((od==0)<<2) | ((oh==0)<<1) | (ow==0);
    gDelta2[i] = fmaxf(gRaw2[i]*gSc2c[oc] + gSh2c[oc], 0.f) - gX2bg[pat*OC2 + oc];
}

__global__ void k_nd3(const float* __restrict__ cw3, const float* __restrict__ cb3) {
    __shared__ float sbg[8*OC2];
    int cs = blockIdx.x, oc = threadIdx.x;
    for (int i = oc; i < 8*OC2; i += 256) sbg[i] = gX2bg[i];
    __syncthreads();
    int dc = cs>>2, hc = (cs>>1)&1, wc = cs&1;
    float acc = 0.f;
    for (int ci = 0; ci < OC2; ci++) {
        const float* wp = &cw3[(oc*OC2 + ci)*27];
        #pragma unroll
        for (int kd = 0; kd < 3; kd++) {
            int zpad = (dc==1 && kd==0) || (dc==2 && kd==2);
            int zb = (dc==1 && kd==1);
            #pragma unroll
            for (int kh = 0; kh < 3; kh++) {
                int ypad = hc && kh==0, yb = hc && kh==1;
                #pragma unroll
                for (int kw = 0; kw < 3; kw++) {
                    int xpad = wc && kw==0, xb = wc && kw==1;
                    if (zpad || ypad || xpad) continue;
                    acc += wp[kd*9 + kh*3 + kw]*sbg[((zb<<2)|(yb<<1)|xb)*OC2 + ci];
                }
            }
        }
    }
    gNd3[cs*OC3 + oc] = cb3[oc] + acc;
}

// conv3: grid (32 ocg(8oc), 2 cihalf, 2 b), 96 thr (48 pos x 2 sub(4oc)); CIB=4
__global__ void k_conv3() {
    __shared__ float sIn[4*567];                // 7 x 9 x 9 per ci
    __shared__ __align__(16) float sW[4*27*8];
    int ocg = blockIdx.x, half = blockIdx.y, b = blockIdx.z;
    int tid = threadIdx.x;
    int sub = tid/48, pos = tid%48;
    int od = pos/16, oh = (pos%16)/4, ow = pos%4;
    unsigned long long a0 = 0ull, a1 = 0ull;
    int cBase = half*128;
    for (int c0 = cBase; c0 < cBase + 128; c0 += 4) {
        __syncthreads();
        for (int i = tid; i < 4*567; i += 96) {
            int cib = i/567, r = i%567;
            int zz = r/81 - 1, rr = r%81, yy = rr/9 - 1, xx = rr%9 - 1;
            float v = 0.f;
            if ((unsigned)zz < 5u && (unsigned)yy < 6u && (unsigned)xx < 6u)
                v = gDelta2[(b*OC2 + c0 + cib)*R2C + zz*36 + yy*6 + xx];
            sIn[i] = v;
        }
        for (int i = tid; i < 4*216; i += 96) {
            int cib = i/216, r = i%216, k = r/8, j = r%8;
            sW[(cib*27 + k)*8 + j] = cwT3[((c0 + cib)*27 + k)*OC3 + ocg*8 + j];
        }
        __syncthreads();
        #pragma unroll
        for (int cib = 0; cib < 4; cib++) {
            const float* bp = sIn + cib*567;
            #pragma unroll
            for (int kd = 0; kd < 3; kd++)
            #pragma unroll
            for (int kh = 0; kh < 3; kh++)
            #pragma unroll
            for (int kw = 0; kw < 3; kw++) {
                float iv = bp[(2*od + kd)*81 + (2*oh + kh)*9 + 2*ow + kw];
                unsigned long long pv = pack2(iv);
                const ulonglong2* wp =
                    (const ulonglong2*)&sW[(cib*27 + kd*9 + kh*3 + kw)*8 + sub*4];
                ulonglong2 w = *wp;
                a0 = ffma2(pv, w.x, a0);
                a1 = ffma2(pv, w.y, a1);
            }
        }
    }
    float* dst = half ? gP3b : gP3a;
    float2 u0 = unpack2(a0), u1 = unpack2(a1);
    float vals[4] = {u0.x, u0.y, u1.x, u1.y};
    #pragma unroll
    for (int j = 0; j < 4; j++) {
        int oc = ocg*8 + sub*4 + j;
        dst[(b*OC3 + oc)*R3C + pos] = vals[j];
    }
}

__device__ __forceinline__ float raw3_at(int b, int oc, int r) {
    int od = r/16, rr = r%16, oh = rr/4, ow = rr%4;
    int dc = (od==0) ? 1 : ((od==2) ? 2 : 0);
    int cs = dc*4 + ((oh==0)<<1) + (ow==0);
    int idx = (b*OC3 + oc)*R3C + r;
    return gP3a[idx] + gP3b[idx] + gNd3[cs*OC3 + oc];
}

__global__ void k_bnc3(const float* __restrict__ cg3, const float* __restrict__ cbe3) {
    int oc = blockIdx.x, tid = threadIdx.x;
    double s = 0.0, q = 0.0;
    for (int i = tid; i < BB*R3C; i += 128) {
        float v = raw3_at(i/R3C, oc, i%R3C);
        s += (double)v; q += (double)v*(double)v;
    }
    __shared__ double ss[128], sq[128];
    ss[tid] = s; sq[tid] = q; __syncthreads();
    for (int st = 64; st; st >>= 1) {
        if (tid < st) { ss[tid] += ss[tid+st]; sq[tid] += sq[tid+st]; }
        __syncthreads();
    }
    if (tid == 0) {
        double S = ss[0], Q = sq[0];
        for (int cs = 0; cs < 12; cs++) {
            int hc = (cs>>1)&1, wc = cs&1;
            int ch = hc?1:15, cw = wc?1:15, dh = hc?1:3, dw = wc?1:3;
            double cnt = 2.0*(ch*cw - dh*dw);
            double bg = (double)gNd3[cs*OC3 + oc];
            S += bg*cnt; Q += bg*bg*cnt;
        }
        double N = 1536.0;
        double mu = S/N, var = Q/N - mu*mu;
        double sc = (double)cg3[oc]*rsqrt(var + 1e-5);
        gSc3c[oc] = (float)sc;
        gSh3c[oc] = (float)((double)cbe3[oc] - mu*sc);
    }
}

__global__ void k_out(float* __restrict__ out) {
    int i = blockIdx.x*256 + threadIdx.x;
    if (i >= BB*OC3*3*256) return;
    int hw = i % 256, od = (i/256) % 3, oc = (i/768) % OC3, b = i/(768*OC3);
    int oh = hw/16, ow = hw%16;
    float sc = gSc3c[oc], sh = gSh3c[oc], raw;
    if (oh < 4 && ow < 4)
        raw = raw3_at(b, oc, od*16 + oh*4 + ow);
    else {
        int dc = (od==0) ? 1 : ((od==2) ? 2 : 0);
        raw = gNd3[(dc*4 + ((oh==0)<<1) + (ow==0))*OC3 + oc];
    }
    out[i] = fmaxf(raw*sc + sh, 0.f);
}

extern "C" void kernel_launch(void* const* d_in, const int* in_sizes, int n_in,
                              void* d_out, int out_size) {
    int base = (n_in >= 25) ? 5 : 2;
    const float* vf   = (const float*)d_in[0];
    const int*  coords= (const int*)d_in[1];
    const float* w1 = (const float*)d_in[base+0];
    const float* b1 = (const float*)d_in[base+1];
    const float* g1 = (const float*)d_in[base+2];
    const float* be1= (const float*)d_in[base+3];
    const float* w2 = (const float*)d_in[base+4];
    const float* b2 = (const float*)d_in[base+5];
    const float* g2 = (const float*)d_in[base+6];
    const float* be2= (const float*)d_in[base+7];
    const float* cw1= (const float*)d_in[base+8];
    const float* cb1= (const float*)d_in[base+9];
    const float* cg1= (const float*)d_in[base+10];
    const float* cbe1=(const float*)d_in[base+11];
    const float* cw2= (const float*)d_in[base+12];
    const float* cb2= (const float*)d_in[base+13];
    const float* cg2= (const float*)d_in[base+14];
    const float* cbe2=(const float*)d_in[base+15];
    const float* cw3= (const float*)d_in[base+16];
    const float* cb3= (const float*)d_in[base+17];
    const float* cg3= (const float*)d_in[base+18];
    const float* cbe3=(const float*)d_in[base+19];
    float* out = (float*)d_out;

    float *dT1, *dT2, *dT3;
    cudaGetSymbolAddress((void**)&dT1, cwT1);
    cudaGetSymbolAddress((void**)&dT2, cwT2);
    cudaGetSymbolAddress((void**)&dT3, cwT3);

    k_init<<<64, 256>>>();
    k_wT<<<(CV2*27*OC1 + 255)/256, 256>>>(cw1, dT1, OC1, CV2);
    k_wT<<<(OC1*27*OC2 + 255)/256, 256>>>(cw2, dT2, OC2, OC1);
    k_wT<<<(OC2*27*OC3 + 255)/256, 256>>>(cw3, dT3, OC3, OC2);
    k_moments<<<128, 256>>>(vf);
    k_bn1<<<1, 64>>>(w1, b1, g1, be1);
    k_vfe<<<BB*NV/VCH, 128>>>(vf, w1, b1, w2, b2);
    k_bn2<<<1, 128>>>(g2, be2);
    k_win<<<(BB*NV + 255)/256, 256>>>(coords);
    k_scatter<<<dim3(CV2, BB), 256>>>();
    k_conv1<<<dim3(16, 10, BB), 128>>>(cb1);
    k_bnc1<<<OC1, 256>>>(cb1, cg1, cbe1);
    k_delta1<<<(BB*OC1*R1C + 255)/256, 256>>>();
    k_bg2<<<8, 256>>>(cw2, cb2);
    k_conv2<<<dim3(64, BB), 192>>>();
    k_bnc2<<<OC2, 128>>>(cg2, cbe2);
    k_delta2<<<(BB*OC2*R2C + 255)/256, 256>>>();
    k_nd3<<<12, 256>>>(cw3, cb3);
    k_conv3<<<dim3(32, 2, BB), 96>>>();
    k_bnc3<<<OC3, 128>>>(cg3, cbe3);
    k_out<<<(BB*OC3*3*256 + 255)/256, 256>>>(out);
}

// round 7
// speedup vs baseline: 3.0592x; 2.9047x over previous
#include <cuda_runtime.h>

#define BB 2
#define NV 12000
#define NP 32
#define CIN 5
#define CV1 64
#define CV2 128
#define GD 20
#define GC 8000
#define OC1 128
#define R1C 1210      // (10,11,11)
#define OC2 256
#define R2C 180       // (5,6,6)
#define OC3 256
#define R3C 48        // (3,4,4)

__device__ double dS1[CIN], dM1[15];
__device__ float  fS2[CV2], fQ2[CV2];
__device__ float  gSc1[CV1], gSh1[CV1];
__device__ float  gY2[BB*NV*CV2];
__device__ float  gSc2[CV2], gSh2[CV2];
__device__ int    gWin[BB*GC];
__device__ float  gSub[BB*CV2*GC];
__device__ float  gRaw1[BB*OC1*R1C];
__device__ float  gSc1c[OC1], gSh1c[OC1], gC1[OC1];
__device__ float  gDelta1[BB*OC1*R1C];
__device__ float  gBg2p[8*OC2];
__device__ float  gBg2[8*OC2];
__device__ float  gP2[2][BB*OC2*R2C];
__device__ float  gSc2c[OC2], gSh2c[OC2];
__device__ float  gX2bg[8*OC2];
__device__ float  gDelta2[BB*OC2*R2C];
__device__ float  gNd3p[12*OC3];
__device__ float  gNd3[12*OC3];
__device__ float  gP3[4][BB*OC3*R3C];
__device__ float  gSc3c[OC3], gSh3c[OC3];
__device__ float  cwT1[CV2*27*OC1];
__device__ float  cwT2[OC1*27*OC2];
__device__ float  cwT3[OC2*27*OC3];

// ---- packed f32x2 helpers ----
__device__ __forceinline__ unsigned long long pack2(float v) {
    unsigned long long p;
    asm("mov.b64 %0, {%1, %1};" : "=l"(p) : "r"(__float_as_uint(v)));
    return p;
}
__device__ __forceinline__ unsigned long long ffma2(unsigned long long a,
                                                    unsigned long long b,
                                                    unsigned long long c) {
    unsigned long long d;
    asm("fma.rn.f32x2 %0, %1, %2, %3;" : "=l"(d) : "l"(a), "l"(b), "l"(c));
    return d;
}
__device__ __forceinline__ float2 unpack2(unsigned long long p) {
    unsigned lo, hi;
    asm("mov.b64 {%0, %1}, %2;" : "=r"(lo), "=r"(hi) : "l"(p));
    float2 r; r.x = __uint_as_float(lo); r.y = __uint_as_float(hi);
    return r;
}

__global__ void k_init() {
    int i = blockIdx.x*256 + threadIdx.x;
    if (i < BB*GC) gWin[i] = -1;
    if (i < CIN) dS1[i] = 0.0;
    if (i < 15)  dM1[i] = 0.0;
    if (i < CV2) { fS2[i] = 0.f; fQ2[i] = 0.f; }
    if (i < 8*OC2)  gBg2p[i] = 0.f;
    if (i < 12*OC3) gNd3p[i] = 0.f;
}

// all 3 weight transposes in one kernel: dst[(ci*27+k)*OC+oc] = src[(oc*IC+ci)*27+k]
__global__ void k_wTall(const float* __restrict__ cw1, const float* __restrict__ cw2,
                        const float* __restrict__ cw3) {
    const int n1 = CV2*27*OC1, n2 = OC1*27*OC2, n3 = OC2*27*OC3;
    int i = blockIdx.x*256 + threadIdx.x;
    if (i < n1) {
        int oc = i % OC1, k = (i/OC1) % 27, ci = i/(OC1*27);
        cwT1[i] = cw1[(oc*CV2 + ci)*27 + k];
    } else if (i < n1 + n2) {
        int j = i - n1;
        int oc = j % OC2, k = (j/OC2) % 27, ci = j/(OC2*27);
        cwT2[j] = cw2[(oc*OC1 + ci)*27 + k];
    } else if (i < n1 + n2 + n3) {
        int j = i - n1 - n2;
        int oc = j % OC3, k = (j/OC3) % 27, ci = j/(OC3*27);
        cwT3[j] = cw3[(oc*OC2 + ci)*27 + k];
    }
}

// input 5x5 moments, fp32 partials, double only at final atomics
__global__ void k_moments(const float* __restrict__ vf) {
    const int rows = BB*NV*NP;
    float s[CIN], m[15];
    #pragma unroll
    for (int i = 0; i < CIN; i++) s[i] = 0.f;
    #pragma unroll
    for (int t = 0; t < 15; t++) m[t] = 0.f;
    for (int r = blockIdx.x*blockDim.x + threadIdx.x; r < rows; r += gridDim.x*blockDim.x) {
        float x[CIN];
        #pragma unroll
        for (int c = 0; c < CIN; c++) x[c] = vf[r*CIN + c];
        int t = 0;
        #pragma unroll
        for (int i = 0; i < CIN; i++) {
            s[i] += x[i];
            #pragma unroll
            for (int j = i; j < CIN; j++) m[t++] += x[i]*x[j];
        }
    }
    for (int off = 16; off; off >>= 1) {
        #pragma unroll
        for (int i = 0; i < CIN; i++) s[i] += __shfl_down_sync(0xffffffffu, s[i], off);
        #pragma unroll
        for (int t = 0; t < 15; t++)  m[t] += __shfl_down_sync(0xffffffffu, m[t], off);
    }
    __shared__ float red[8][20];
    int w = threadIdx.x >> 5, l = threadIdx.x & 31;
    if (l == 0) {
        #pragma unroll
        for (int i = 0; i < CIN; i++) red[w][i] = s[i];
        #pragma unroll
        for (int t = 0; t < 15; t++)  red[w][5+t] = m[t];
    }
    __syncthreads();
    if (threadIdx.x < 20) {
        double a = 0.0;
        #pragma unroll
        for (int ww = 0; ww < 8; ww++) a += (double)red[ww][threadIdx.x];
        if (threadIdx.x < 5) atomicAdd(&dS1[threadIdx.x], a);
        else                 atomicAdd(&dM1[threadIdx.x-5], a);
    }
}

__global__ void k_bn1(const float* __restrict__ w1, const float* __restrict__ b1,
                      const float* __restrict__ g1, const float* __restrict__ be1) {
    int oc = threadIdx.x; if (oc >= CV1) return;
    const double N = (double)BB*NV*NP;
    double mx[CIN], w[CIN];
    #pragma unroll
    for (int c = 0; c < CIN; c++) { mx[c] = dS1[c]/N; w[c] = (double)w1[oc*CIN+c]; }
    double bb = (double)b1[oc];
    double mu = bb, ey2 = bb*bb;
    #pragma unroll
    for (int c = 0; c < CIN; c++) { mu += w[c]*mx[c]; ey2 += 2.0*bb*w[c]*mx[c]; }
    int t = 0;
    #pragma unroll
    for (int i = 0; i < CIN; i++)
        #pragma unroll
        for (int j = i; j < CIN; j++) {
            double Exx = dM1[t++]/N;
            ey2 += (i==j ? 1.0 : 2.0)*w[i]*w[j]*Exx;
        }
    double var = ey2 - mu*mu;
    double sc = (double)g1[oc]*rsqrt(var + 1e-5);
    gSc1[oc] = (float)sc;
    gSh1[oc] = (float)((double)be1[oc] - mu*sc);
}

// fused VFE1+VFE2; 2 voxels per barrier; w2 staged via padded smem; fp32 stats
#define VCH 24
__global__ void k_vfe(const float* __restrict__ vf,
                      const float* __restrict__ w1, const float* __restrict__ b1,
                      const float* __restrict__ w2, const float* __restrict__ b2) {
    __shared__ float sw2[128*65];
    __shared__ float sx[2][NP*CIN];
    __shared__ __align__(8) float sf1[CV1*2];
    int tid = threadIdx.x;
    for (int i = tid; i < 128*64; i += 128)
        sw2[(i/64)*65 + (i%64)] = w2[i];
    float bb2 = b2[tid];
    int half = tid >> 6, oc1 = tid & 63;
    float w1r[CIN];
    #pragma unroll
    for (int c = 0; c < CIN; c++) w1r[c] = w1[oc1*CIN + c];
    float bb1 = b1[oc1], sc1 = gSc1[oc1], sh1 = gSh1[oc1];
    float s = 0.f, q = 0.f;
    int base = blockIdx.x*VCH;
    for (int t = 0; t < VCH; t += 2) {
        int v0 = base + t;
        __syncthreads();
        for (int i = tid; i < 2*NP*CIN; i += 128) sx[i/160][i%160] = vf[v0*NP*CIN + i];
        __syncthreads();
        {   // VFE1: thread processes voxel 'half', channel oc1
            float m = 0.f;
            #pragma unroll 4
            for (int p = 0; p < NP; p++) {
                float y = bb1;
                #pragma unroll
                for (int c = 0; c < CIN; c++) y += w1r[c]*sx[half][p*CIN + c];
                m = fmaxf(m, fmaxf(y*sc1 + sh1, 0.f));
            }
            sf1[oc1*2 + half] = m;
        }
        __syncthreads();
        {   // VFE2 both voxels via packed ffma2
            unsigned long long acc = pack2(bb2);
            const unsigned long long* fp = (const unsigned long long*)sf1;
            #pragma unroll
            for (int c = 0; c < CV1; c++)
                acc = ffma2(pack2(sw2[tid*65 + c]), fp[c], acc);
            float2 y = unpack2(acc);
            gY2[v0*CV2 + tid]     = y.x;
            gY2[(v0+1)*CV2 + tid] = y.y;
            s += y.x + y.y; q += y.x*y.x + y.y*y.y;
        }
    }
    atomicAdd(&fS2[tid], s); atomicAdd(&fQ2[tid], q);
}

__global__ void k_bn2(const float* __restrict__ g2, const float* __restrict__ be2) {
    int oc = threadIdx.x;
    double N = (double)BB*NV;
    double mu = (double)fS2[oc]/N, var = (double)fQ2[oc]/N - mu*mu;
    double sc = (double)g2[oc]*rsqrt(var + 1e-5);
    gSc2[oc] = (float)sc;
    gSh2[oc] = (float)((double)be2[oc] - mu*sc);
}

__global__ void k_win(const int* __restrict__ coords) {
    int i = blockIdx.x*256 + threadIdx.x; if (i >= BB*NV) return;
    int b = i/NV;
    int d = coords[i*3], h = coords[i*3+1], w = coords[i*3+2];
    if ((unsigned)d < GD && (unsigned)h < GD && (unsigned)w < GD)
        atomicMax(&gWin[b*GC + (d*GD + h)*GD + w], i % NV);
}

__global__ void k_scatter() {
    int ch = blockIdx.x, b = blockIdx.y;
    float sc = gSc2[ch], sh = gSh2[ch];
    for (int cell = threadIdx.x; cell < GC; cell += 256) {
        int win = gWin[b*GC + cell];
        float v = 0.f;
        if (win >= 0) v = fmaxf(gY2[(b*NV + win)*CV2 + ch]*sc + sh, 0.f);
        gSub[(b*CV2 + ch)*GC + cell] = v;
    }
}

// conv1: grid (16 ocg, 10 od, 2 b), 128 thr; CIB=4; f32x2
__global__ void k_conv1(const float* __restrict__ cb1) {
    __shared__ float sIn[4*1587];
    __shared__ __align__(16) float sW[4*27*8];
    int ocg = blockIdx.x, od = blockIdx.y, b = blockIdx.z;
    int tid = threadIdx.x;
    int oh = tid/11, ow = tid%11;
    bool act = tid < 121;
    unsigned long long acc[4] = {0ull, 0ull, 0ull, 0ull};
    for (int c0 = 0; c0 < CV2; c0 += 4) {
        __syncthreads();
        for (int i = tid; i < 4*1587; i += 128) {
            int cib = i/1587, r = i%1587;
            int kd = r/529, rr = r%529, yy = rr/23 - 1, xx = rr%23 - 1;
            int z = 2*od - 1 + kd;
            float v = 0.f;
            if ((unsigned)z < GD && (unsigned)yy < GD && (unsigned)xx < GD)
                v = gSub[(b*CV2 + c0 + cib)*GC + (z*GD + yy)*GD + xx];
            sIn[i] = v;
        }
        for (int i = tid; i < 4*216; i += 128) {
            int cib = i/216, r = i%216, k = r/8, j = r%8;
            sW[(cib*27 + k)*8 + j] = cwT1[((c0 + cib)*27 + k)*OC1 + ocg*8 + j];
        }
        __syncthreads();
        if (act) {
            #pragma unroll
            for (int cib = 0; cib < 4; cib++) {
                const float* bp = sIn + cib*1587;
                #pragma unroll
                for (int kd = 0; kd < 3; kd++)
                #pragma unroll
                for (int kh = 0; kh < 3; kh++)
                #pragma unroll
                for (int kw = 0; kw < 3; kw++) {
                    float iv = bp[kd*529 + (2*oh + kh)*23 + 2*ow + kw];
                    unsigned long long pv = pack2(iv);
                    const ulonglong2* wp =
                        (const ulonglong2*)&sW[(cib*27 + kd*9 + kh*3 + kw)*8];
                    ulonglong2 wa = wp[0], wb = wp[1];
                    acc[0] = ffma2(pv, wa.x, acc[0]);
                    acc[1] = ffma2(pv, wa.y, acc[1]);
                    acc[2] = ffma2(pv, wb.x, acc[2]);
                    acc[3] = ffma2(pv, wb.y, acc[3]);
                }
            }
        }
    }
    if (act) {
        float2 u0 = unpack2(acc[0]), u1 = unpack2(acc[1]);
        float2 u2 = unpack2(acc[2]), u3 = unpack2(acc[3]);
        float vals[8] = {u0.x,u0.y,u1.x,u1.y,u2.x,u2.y,u3.x,u3.y};
        #pragma unroll
        for (int j = 0; j < 8; j++) {
            int oc = ocg*8 + j;
            gRaw1[(b*OC1 + oc)*R1C + od*121 + tid] = vals[j] + cb1[oc];
        }
    }
}

__global__ void k_bnc1(const float* __restrict__ cb1, const float* __restrict__ cg1,
                       const float* __restrict__ cbe1) {
    int oc = blockIdx.x, tid = threadIdx.x;
    float s = 0.f, q = 0.f;
    for (int i = tid; i < BB*R1C; i += 256) {
        float v = gRaw1[(i/R1C*OC1 + oc)*R1C + i%R1C];
        s += v; q += v*v;
    }
    __shared__ double ss[256], sq[256];
    ss[tid] = (double)s; sq[tid] = (double)q; __syncthreads();
    for (int st = 128; st; st >>= 1) {
        if (tid < st) { ss[tid] += ss[tid+st]; sq[tid] += sq[tid+st]; }
        __syncthreads();
    }
    if (tid == 0) {
        double N = 81920.0, bgn = N - BB*R1C;
        double bg = (double)cb1[oc];
        double mu = (ss[0] + bg*bgn)/N;
        double var = (sq[0] + bg*bg*bgn)/N - mu*mu;
        double sc = (double)cg1[oc]*rsqrt(var + 1e-5);
        double sh = (double)cbe1[oc] - mu*sc;
        gSc1c[oc] = (float)sc; gSh1c[oc] = (float)sh;
        double c1 = bg*sc + sh;
        gC1[oc] = (float)(c1 > 0.0 ? c1 : 0.0);
    }
}

__global__ void k_delta1() {
    int i = blockIdx.x*256 + threadIdx.x;
    if (i >= BB*OC1*R1C) return;
    int oc = (i/R1C) % OC1;
    gDelta1[i] = fmaxf(gRaw1[i]*gSc1c[oc] + gSh1c[oc], 0.f) - gC1[oc];
}

// conv2 background partials: coalesced cwT2, all 8 patterns per load
__global__ void k_bg2() {
    __shared__ float sc1[OC1];
    int oc = threadIdx.x, cq = blockIdx.x;
    for (int i = oc; i < OC1; i += 256) sc1[i] = gC1[i];
    __syncthreads();
    float acc[8] = {0,0,0,0,0,0,0,0};
    for (int cc = 0; cc < 8; cc++) {
        int ci = cq*8 + cc;
        float cv = sc1[ci];
        const float* wp = &cwT2[ci*27*OC2 + oc];
        #pragma unroll
        for (int k = 0; k < 27; k++) {
            float v = wp[k*OC2]*cv;
            int kd = k/9, kh = (k/3)%3, kw = k%3;
            #pragma unroll
            for (int pat = 0; pat < 8; pat++) {
                bool fd = pat&4, fh = pat&2, fw = pat&1;
                if (!((fd && kd==0) || (fh && kh==0) || (fw && kw==0)))
                    acc[pat] += v;
            }
        }
    }
    #pragma unroll
    for (int pat = 0; pat < 8; pat++)
        atomicAdd(&gBg2p[pat*OC2 + oc], acc[pat]);
}

__global__ void k_finbg(const float* __restrict__ cb2) {
    int i = blockIdx.x*256 + threadIdx.x;
    if (i < 8*OC2) gBg2[i] = gBg2p[i] + cb2[i % OC2];
}

// conv2: grid (64 ocq, 2 cihalf, 2 b), 192 thr; partial sums (no bg)
__global__ void k_conv2() {
    __shared__ float sIn[4*1859];
    __shared__ __align__(16) float sW[4*27*4];
    int ocq = blockIdx.x, half = blockIdx.y, b = blockIdx.z;
    int tid = threadIdx.x;
    int pos = tid;
    int od = pos/36, oh = (pos%36)/6, ow = pos%6;
    bool act = tid < R2C;
    unsigned long long a0 = 0ull, a1 = 0ull;
    int cBase = half*64;
    for (int c0 = cBase; c0 < cBase + 64; c0 += 4) {
        __syncthreads();
        for (int i = tid; i < 4*1859; i += 192) {
            int cib = i/1859, r = i%1859;
            int zz = r/169 - 1, rr = r%169, yy = rr/13 - 1, xx = rr%13 - 1;
            float v = 0.f;
            if ((unsigned)zz < 10u && (unsigned)yy < 11u && (unsigned)xx < 11u)
                v = gDelta1[(b*OC1 + c0 + cib)*R1C + zz*121 + yy*11 + xx];
            sIn[i] = v;
        }
        for (int i = tid; i < 4*108; i += 192) {
            int cib = i/108, r = i%108, k = r/4, j = r%4;
            sW[(cib*27 + k)*4 + j] = cwT2[((c0 + cib)*27 + k)*OC2 + ocq*4 + j];
        }
        __syncthreads();
        if (act) {
            #pragma unroll
            for (int cib = 0; cib < 4; cib++) {
                const float* bp = sIn + cib*1859;
                #pragma unroll
                for (int kd = 0; kd < 3; kd++)
                #pragma unroll
                for (int kh = 0; kh < 3; kh++)
                #pragma unroll
                for (int kw = 0; kw < 3; kw++) {
                    float iv = bp[(2*od + kd)*169 + (2*oh + kh)*13 + 2*ow + kw];
                    unsigned long long pv = pack2(iv);
                    const ulonglong2* wp =
                        (const ulonglong2*)&sW[(cib*27 + kd*9 + kh*3 + kw)*4];
                    ulonglong2 w = *wp;
                    a0 = ffma2(pv, w.x, a0);
                    a1 = ffma2(pv, w.y, a1);
                }
            }
        }
    }
    if (act) {
        float2 u0 = unpack2(a0), u1 = unpack2(a1);
        float vals[4] = {u0.x, u0.y, u1.x, u1.y};
        #pragma unroll
        for (int j = 0; j < 4; j++) {
            int oc = ocq*4 + j;
            gP2[half][(b*OC2 + oc)*R2C + pos] = vals[j];
        }
    }
}

__device__ __forceinline__ float raw2_at(int b, int oc, int r) {
    int od = r/36, oh = (r%36)/6, ow = r%6;
    int pat = ((od==0)<<2) | ((oh==0)<<1) | (ow==0);
    int idx = (b*OC2 + oc)*R2C + r;
    return gP2[0][idx] + gP2[1][idx] + gBg2[pat*OC2 + oc];
}

__global__ void k_bnc2(const float* __restrict__ cg2, const float* __restrict__ cbe2) {
    int oc = blockIdx.x, tid = threadIdx.x;
    float s = 0.f, q = 0.f;
    for (int i = tid; i < BB*R2C; i += 128) {
        float v = raw2_at(i/R2C, oc, i%R2C);
        s += v; q += v*v;
    }
    __shared__ double ss[128], sq[128];
    ss[tid] = (double)s; sq[tid] = (double)q; __syncthreads();
    for (int st = 64; st; st >>= 1) {
        if (tid < st) { ss[tid] += ss[tid+st]; sq[tid] += sq[tid+st]; }
        __syncthreads();
    }
    if (tid == 0) {
        double S = ss[0], Q = sq[0];
        for (int pat = 0; pat < 8; pat++) {
            int fd = (pat>>2)&1, fh = (pat>>1)&1, fw = pat&1;
            int cd = fd?1:4, ch = fh?1:31, cw = fw?1:31;
            int dh = fh?1:5, dw = fw?1:5;
            double cnt = 2.0*cd*(ch*cw - dh*dw);
            double bg = (double)gBg2[pat*OC2 + oc];
            S += bg*cnt; Q += bg*bg*cnt;
        }
        double N = 10240.0;
        double mu = S/N, var = Q/N - mu*mu;
        double sc = (double)cg2[oc]*rsqrt(var + 1e-5);
        double sh = (double)cbe2[oc] - mu*sc;
        gSc2c[oc] = (float)sc; gSh2c[oc] = (float)sh;
        for (int pat = 0; pat < 8; pat++) {
            double v = (double)gBg2[pat*OC2 + oc]*sc + sh;
            gX2bg[pat*OC2 + oc] = (float)(v > 0.0 ? v : 0.0);
        }
    }
}

__global__ void k_delta2() {
    int i = blockIdx.x*256 + threadIdx.x;
    if (i >= BB*OC2*R2C) return;
    int r = i % R2C, oc = (i/R2C) % OC2, b = i/(R2C*OC2);
    int od = r/36, oh = (r%36)/6, ow = r%6;
    int pat = ((od==0)<<2) | ((oh==0)<<1) | (ow==0);
    gDelta2[i] = fmaxf(raw2_at(b, oc, r)*gSc2c[oc] + gSh2c[oc], 0.f)
                 - gX2bg[pat*OC2 + oc];
}

// conv3 no-data backgrounds: coalesced cwT3, all 12 cases per load
__global__ void k_nd3() {
    __shared__ float sbg[8*OC2];
    int oc = threadIdx.x, cq = blockIdx.x;
    for (int i = oc; i < 8*OC2; i += 256) sbg[i] = gX2bg[i];
    __syncthreads();
    float acc[12];
    #pragma unroll
    for (int j = 0; j < 12; j++) acc[j] = 0.f;
    for (int cc = 0; cc < 8; cc++) {
        int ci = cq*8 + cc;
        const float* wp = &cwT3[ci*27*OC3 + oc];
        #pragma unroll
        for (int k = 0; k < 27; k++) {
            float w = wp[k*OC3];
            int kd = k/9, kh = (k/3)%3, kw = k%3;
            #pragma unroll
            for (int cs = 0; cs < 12; cs++) {
                int dc = cs>>2, hc = (cs>>1)&1, wc = cs&1;
                bool zpad = (dc==1 && kd==0) || (dc==2 && kd==2);
                bool ypad = hc && kh==0, xpad = wc && kw==0;
                if (!(zpad || ypad || xpad)) {
                    int zb = (dc==1 && kd==1), yb = hc && kh==1, xb = wc && kw==1;
                    acc[cs] += w*sbg[((zb<<2)|(yb<<1)|xb)*OC2 + ci];
                }
            }
        }
    }
    #pragma unroll
    for (int cs = 0; cs < 12; cs++)
        atomicAdd(&gNd3p[cs*OC3 + oc], acc[cs]);
}

__global__ void k_finnd(const float* __restrict__ cb3) {
    int i = blockIdx.x*256 + threadIdx.x;
    if (i < 12*OC3) gNd3[i] = gNd3p[i] + cb3[i % OC3];
}

// conv3: grid (32 ocg(8oc), 4 ciquarter, 2 b), 96 thr (48 pos x 2 sub(4oc))
__global__ void k_conv3() {
    __shared__ float sIn[4*567];
    __shared__ __align__(16) float sW[4*27*8];
    int ocg = blockIdx.x, qq = blockIdx.y, b = blockIdx.z;
    int tid = threadIdx.x;
    int sub = tid/48, pos = tid%48;
    int od = pos/16, oh = (pos%16)/4, ow = pos%4;
    unsigned long long a0 = 0ull, a1 = 0ull;
    int cBase = qq*64;
    for (int c0 = cBase; c0 < cBase + 64; c0 += 4) {
        __syncthreads();
        for (int i = tid; i < 4*567; i += 96) {
            int cib = i/567, r = i%567;
            int zz = r/81 - 1, rr = r%81, yy = rr/9 - 1, xx = rr%9 - 1;
            float v = 0.f;
            if ((unsigned)zz < 5u && (unsigned)yy < 6u && (unsigned)xx < 6u)
                v = gDelta2[(b*OC2 + c0 + cib)*R2C + zz*36 + yy*6 + xx];
            sIn[i] = v;
        }
        for (int i = tid; i < 4*216; i += 96) {
            int cib = i/216, r = i%216, k = r/8, j = r%8;
            sW[(cib*27 + k)*8 + j] = cwT3[((c0 + cib)*27 + k)*OC3 + ocg*8 + j];
        }
        __syncthreads();
        #pragma unroll
        for (int cib = 0; cib < 4; cib++) {
            const float* bp = sIn + cib*567;
            #pragma unroll
            for (int kd = 0; kd < 3; kd++)
            #pragma unroll
            for (int kh = 0; kh < 3; kh++)
            #pragma unroll
            for (int kw = 0; kw < 3; kw++) {
                float iv = bp[(2*od + kd)*81 + (2*oh + kh)*9 + 2*ow + kw];
                unsigned long long pv = pack2(iv);
                const ulonglong2* wp =
                    (const ulonglong2*)&sW[(cib*27 + kd*9 + kh*3 + kw)*8 + sub*4];
                ulonglong2 w = *wp;
                a0 = ffma2(pv, w.x, a0);
                a1 = ffma2(pv, w.y, a1);
            }
        }
    }
    float2 u0 = unpack2(a0), u1 = unpack2(a1);
    float vals[4] = {u0.x, u0.y, u1.x, u1.y};
    #pragma unroll
    for (int j = 0; j < 4; j++) {
        int oc = ocg*8 + sub*4 + j;
        gP3[qq][(b*OC3 + oc)*R3C + pos] = vals[j];
    }
}

__device__ __forceinline__ float raw3_at(int b, int oc, int r) {
    int od = r/16, rr = r%16, oh = rr/4, ow = rr%4;
    int dc = (od==0) ? 1 : ((od==2) ? 2 : 0);
    int cs = dc*4 + ((oh==0)<<1) + (ow==0);
    int idx = (b*OC3 + oc)*R3C + r;
    return gP3[0][idx] + gP3[1][idx] + gP3[2][idx] + gP3[3][idx] + gNd3[cs*OC3 + oc];
}

__global__ void k_bnc3(const float* __restrict__ cg3, const float* __restrict__ cbe3) {
    int oc = blockIdx.x, tid = threadIdx.x;
    float s = 0.f, q = 0.f;
    for (int i = tid; i < BB*R3C; i += 128) {
        float v = raw3_at(i/R3C, oc, i%R3C);
        s += v; q += v*v;
    }
    __shared__ double ss[128], sq[128];
    ss[tid] = (double)s; sq[tid] = (double)q; __syncthreads();
    for (int st = 64; st; st >>= 1) {
        if (tid < st) { ss[tid] += ss[tid+st]; sq[tid] += sq[tid+st]; }
        __syncthreads();
    }
    if (tid == 0) {
        double S = ss[0], Q = sq[0];
        for (int cs = 0; cs < 12; cs++) {
            int hc = (cs>>1)&1, wc = cs&1;
            int ch = hc?1:15, cw = wc?1:15, dh = hc?1:3, dw = wc?1:3;
            double cnt = 2.0*(ch*cw - dh*dw);
            double bg = (double)gNd3[cs*OC3 + oc];
            S += bg*cnt; Q += bg*bg*cnt;
        }
        double N = 1536.0;
        double mu = S/N, var = Q/N - mu*mu;
        double sc = (double)cg3[oc]*rsqrt(var + 1e-5);
        gSc3c[oc] = (float)sc;
        gSh3c[oc] = (float)((double)cbe3[oc] - mu*sc);
    }
}

__global__ void k_out(float* __restrict__ out) {
    int i = blockIdx.x*256 + threadIdx.x;
    if (i >= BB*OC3*3*256) return;
    int hw = i % 256, od = (i/256) % 3, oc = (i/768) % OC3, b = i/(768*OC3);
    int oh = hw/16, ow = hw%16;
    float sc = gSc3c[oc], sh = gSh3c[oc], raw;
    if (oh < 4 && ow < 4)
        raw = raw3_at(b, oc, od*16 + oh*4 + ow);
    else {
        int dc = (od==0) ? 1 : ((od==2) ? 2 : 0);
        raw = gNd3[(dc*4 + ((oh==0)<<1) + (ow==0))*OC3 + oc];
    }
    out[i] = fmaxf(raw*sc + sh, 0.f);
}

extern "C" void kernel_launch(void* const* d_in, const int* in_sizes, int n_in,
                              void* d_out, int out_size) {
    int base = (n_in >= 25) ? 5 : 2;
    const float* vf   = (const float*)d_in[0];
    const int*  coords= (const int*)d_in[1];
    const float* w1 = (const float*)d_in[base+0];
    const float* b1 = (const float*)d_in[base+1];
    const float* g1 = (const float*)d_in[base+2];
    const float* be1= (const float*)d_in[base+3];
    const float* w2 = (const float*)d_in[base+4];
    const float* b2 = (const float*)d_in[base+5];
    const float* g2 = (const float*)d_in[base+6];
    const float* be2= (const float*)d_in[base+7];
    const float* cw1= (const float*)d_in[base+8];
    const float* cb1= (const float*)d_in[base+9];
    const float* cg1= (const float*)d_in[base+10];
    const float* cbe1=(const float*)d_in[base+11];
    const float* cw2= (const float*)d_in[base+12];
    const float* cb2= (const float*)d_in[base+13];
    const float* cg2= (const float*)d_in[base+14];
    const float* cbe2=(const float*)d_in[base+15];
    const float* cw3= (const float*)d_in[base+16];
    const float* cb3= (const float*)d_in[base+17];
    const float* cg3= (const float*)d_in[base+18];
    const float* cbe3=(const float*)d_in[base+19];
    float* out = (float*)d_out;

    const int nT = CV2*27*OC1 + OC1*27*OC2 + OC2*27*OC3;
    k_init<<<64, 256>>>();
    k_wTall<<<(nT + 255)/256, 256>>>(cw1, cw2, cw3);
    k_moments<<<128, 256>>>(vf);
    k_bn1<<<1, 64>>>(w1, b1, g1, be1);
    k_vfe<<<BB*NV/VCH, 128>>>(vf, w1, b1, w2, b2);
    k_bn2<<<1, 128>>>(g2, be2);
    k_win<<<(BB*NV + 255)/256, 256>>>(coords);
    k_scatter<<<dim3(CV2, BB), 256>>>();
    k_conv1<<<dim3(16, 10, BB), 128>>>(cb1);
    k_bnc1<<<OC1, 256>>>(cb1, cg1, cbe1);
    k_delta1<<<(BB*OC1*R1C + 255)/256, 256>>>();
    k_bg2<<<16, 256>>>();
    k_finbg<<<8, 256>>>(cb2);
    k_conv2<<<dim3(64, 2, BB), 192>>>();
    k_bnc2<<<OC2, 128>>>(cg2, cbe2);
    k_delta2<<<(BB*OC2*R2C + 255)/256, 256>>>();
    k_nd3<<<32, 256>>>();
    k_finnd<<<12, 256>>>(cb3);
    k_conv3<<<dim3(32, 4, BB), 96>>>();
    k_bnc3<<<OC3, 128>>>(cg3, cbe3);
    k_out<<<(BB*OC3*3*256 + 255)/256, 256>>>(out);
}